// round 12
// baseline (speedup 1.0000x reference)
#include <cuda_runtime.h>
#include <cstdint>

#define N_NODES 50000
#define EMAX 1600000
#define LDA 144
#define SB 512
#define NB 98            // ceil(N_NODES/512)
#define GBLK_TC 391      // ceil(N_NODES/128)

// ---------------- scratch (static __device__, no allocation) ----------------
__device__ float g_A[N_NODES * LDA];      // layer-1 GEMM input, stride 144 (cols 134..143 stay 0)
__device__ float g_h1[N_NODES * 128];     // relu output layer 1
__device__ float g_uv[N_NODES * 128];     // cols 0..63 = h1@W2_nbr, cols 64..127 = h1@W2_root
__device__ float g_h2[N_NODES * 64];      // final embeddings
__device__ float g_deginv[N_NODES];
__device__ int   g_deg[N_NODES];
__device__ int   g_cur[N_NODES];
__device__ int   g_rowptr[N_NODES + 1];
__device__ int   g_bsum[NB];
__device__ int   g_boff[NB];
__device__ int   g_csr[EMAX];             // src ids bucketed by dst
__device__ int   g_eid[EMAX];             // original edge id bucketed by dst
__device__ float g_W1hi[144 * 128];
__device__ float g_W1lo[144 * 128];
__device__ float g_W2hi[128 * 128];
__device__ float g_W2lo[128 * 128];

// ---------------- tf32 helpers ----------------
__device__ __forceinline__ uint32_t tf32_of(float f) {
    uint32_t r; asm("cvt.rna.tf32.f32 %0, %1;" : "=r"(r) : "f"(f)); return r;
}
__device__ __forceinline__ void mma_tf32(float* c, const uint32_t* a, float b0, float b1) {
    asm volatile(
        "mma.sync.aligned.m16n8k8.row.col.f32.tf32.tf32.f32 "
        "{%0,%1,%2,%3}, {%4,%5,%6,%7}, {%8,%9}, {%0,%1,%2,%3};"
        : "+f"(c[0]), "+f"(c[1]), "+f"(c[2]), "+f"(c[3])
        : "r"(a[0]), "r"(a[1]), "r"(a[2]), "r"(a[3]),
          "r"(__float_as_uint(b0)), "r"(__float_as_uint(b1)));
}

// ---------------- small kernels ----------------
// fused: zero counters + build split weights
__global__ void k_prepw(const float* __restrict__ W1r, const float* __restrict__ W1n,
                        const float* __restrict__ W2r, const float* __restrict__ W2n) {
    int t0 = blockIdx.x * blockDim.x + threadIdx.x;
    int stride = gridDim.x * blockDim.x;
    for (int i = t0; i < N_NODES; i += stride) { g_deg[i] = 0; g_cur[i] = 0; }
    for (int i = t0; i < 144 * 128; i += stride) {
        int r = i >> 7, c = i & 127;
        float v = 0.0f;
        if (r < 66) v = W1r[r * 128 + c];
        else if (r >= 68 && r < 134) v = W1n[(r - 68) * 128 + c];
        float hi = __uint_as_float(tf32_of(v));
        g_W1hi[i] = hi;
        g_W1lo[i] = __uint_as_float(tf32_of(v - hi));
    }
    for (int i = t0; i < 128 * 128; i += stride) {
        int r = i >> 7, c = i & 127;
        float v = (c < 64) ? W2n[r * 64 + c] : W2r[r * 64 + (c - 64)];
        float hi = __uint_as_float(tf32_of(v));
        g_W2hi[i] = hi;
        g_W2lo[i] = __uint_as_float(tf32_of(v - hi));
    }
}

__global__ void k_deg(const int* __restrict__ dst, int E) {
    int i = blockIdx.x * blockDim.x + threadIdx.x;
    if (i < E) atomicAdd(&g_deg[dst[i]], 1);
}

__global__ void k_scan1() {
    __shared__ int s[SB];
    int tid = threadIdx.x;
    int i = blockIdx.x * SB + tid;
    int v = (i < N_NODES) ? g_deg[i] : 0;
    s[tid] = v;
    __syncthreads();
    #pragma unroll
    for (int off = 1; off < SB; off <<= 1) {
        int t = (tid >= off) ? s[tid - off] : 0;
        __syncthreads();
        s[tid] += t;
        __syncthreads();
    }
    if (i < N_NODES) g_rowptr[i] = s[tid] - v;
    if (tid == SB - 1) g_bsum[blockIdx.x] = s[tid];
}

__global__ void k_scan2() {
    if (threadIdx.x == 0 && blockIdx.x == 0) {
        int run = 0;
        for (int b = 0; b < NB; b++) { g_boff[b] = run; run += g_bsum[b]; }
    }
}

__global__ void k_scan3(int E) {
    int i = blockIdx.x * blockDim.x + threadIdx.x;
    if (i < N_NODES) {
        g_rowptr[i] += g_boff[i / SB];
        g_deginv[i] = 1.0f / fmaxf((float)g_deg[i], 1.0f);
    }
    if (i == 0) g_rowptr[N_NODES] = E;
}

__global__ void k_fillcsr(const int* __restrict__ src, const int* __restrict__ dst, int E) {
    int e = blockIdx.x * blockDim.x + threadIdx.x;
    if (e >= E) return;
    int d = dst[e];
    int ofs = atomicAdd(&g_cur[d], 1);
    int pos = g_rowptr[d] + ofs;
    g_csr[pos] = src[e];
    g_eid[pos] = e;
}

// A cols 0..67 = concat(x, pos, 0, 0)
__global__ void k_buildA1(const float* __restrict__ x, const float* __restrict__ pos) {
    int i = blockIdx.x * blockDim.x + threadIdx.x;
    if (i >= N_NODES * 68) return;
    int n = i / 68, c = i % 68;
    float v = 0.0f;
    if (c < 64) v = x[n * 64 + c];
    else if (c < 66) v = pos[n * 2 + (c - 64)];
    g_A[(size_t)n * LDA + c] = v;
}

// ---------------- gather-side aggregation, layer 1 ----------------
__global__ __launch_bounds__(256) void k_agg1(const float* __restrict__ x,
                                              const float* __restrict__ pos) {
    int gt = blockIdx.x * blockDim.x + threadIdx.x;
    int w = gt >> 5, lane = gt & 31;
    if (w >= N_NODES) return;
    int start = g_rowptr[w], end = g_rowptr[w + 1];
    float ax = 0.f, ay = 0.f, px = 0.f, py = 0.f;
    const float2* x2 = (const float2*)x;
    const float2* p2 = (const float2*)pos;
    for (int i = start; i < end; i += 32) {
        int m = min(32, end - i);
        int eid = (i + lane < end) ? g_csr[i + lane] : 0;
        for (int j = 0; j < m; j++) {
            int s = __shfl_sync(0xffffffffu, eid, j);
            float2 v = __ldg(x2 + (size_t)s * 32 + lane);
            ax += v.x; ay += v.y;
            if (lane == 0) { float2 p = __ldg(p2 + s); px += p.x; py += p.y; }
        }
    }
    float di = g_deginv[w];
    float* rowp = g_A + (size_t)w * LDA;
    rowp[68 + lane * 2]     = ax * di;
    rowp[68 + lane * 2 + 1] = ay * di;
    if (lane == 0) { rowp[132] = px * di; rowp[133] = py * di; }
}

// ---------------- tensor-core GEMM: C[M,128] = A[M,K] @ B[K,128] ----------------
// TF32 mma.m16n8k8, 3-term split. 128x128 tile, 8 warps, 16 n-tiles per warp.
// B smem uses permuted columns p(n) = (n&7)*16 + (n>>3), stride 132:
// a thread's 16 fragment values (n = t*8+gid, t=0..15) are contiguous -> LDS.128.
template <int MODE>
__global__ __launch_bounds__(256) void k_gemm_tc(const float* __restrict__ bias) {
    const int K   = (MODE == 0) ? 144 : 128;
    const int lda = (MODE == 0) ? 144 : 128;
    const float* __restrict__ A   = (MODE == 0) ? g_A : g_h1;
    const float* __restrict__ Bhi = (MODE == 0) ? g_W1hi : g_W2hi;
    const float* __restrict__ Blo = (MODE == 0) ? g_W1lo : g_W2lo;
    float* __restrict__ C         = (MODE == 0) ? g_h1 : g_uv;

    __shared__ float As[16][136];    // [k][m]
    __shared__ float Bth[16][132];   // [k][p(n)] hi
    __shared__ float Btl[16][132];   // [k][p(n)] lo

    int tid  = threadIdx.x;
    int wid  = tid >> 5, lane = tid & 31;
    int tg   = lane & 3, gid = lane >> 2;
    int m0   = blockIdx.x * 128;

    // A loader: 2 threads/row, each 2 float4 (k-halves 0-7 / 8-15)
    int arow = tid >> 1;
    int ak   = (tid & 1) * 8;
    int a_grow = min(m0 + arow, N_NODES - 1);
    // B loader: brow = tid>>4 (0..15), cols (tid&15)*8 .. +7 -> permuted scalar stores
    int brow = tid >> 4;
    int bq   = tid & 15;              // col block: n = bq*8 + c, p(n) = c*16 + bq

    float acc[16][4];
    #pragma unroll
    for (int t = 0; t < 16; t++)
        #pragma unroll
        for (int i = 0; i < 4; i++) acc[t][i] = 0.0f;

    for (int k0 = 0; k0 < K; k0 += 16) {
        float4 av0 = *(const float4*)(A + (size_t)a_grow * lda + k0 + ak);
        float4 av1 = *(const float4*)(A + (size_t)a_grow * lda + k0 + ak + 4);
        float4 bh0 = *(const float4*)(Bhi + (size_t)(k0 + brow) * 128 + bq * 8);
        float4 bh1 = *(const float4*)(Bhi + (size_t)(k0 + brow) * 128 + bq * 8 + 4);
        float4 bl0 = *(const float4*)(Blo + (size_t)(k0 + brow) * 128 + bq * 8);
        float4 bl1 = *(const float4*)(Blo + (size_t)(k0 + brow) * 128 + bq * 8 + 4);
        __syncthreads();
        As[ak + 0][arow] = av0.x; As[ak + 1][arow] = av0.y;
        As[ak + 2][arow] = av0.z; As[ak + 3][arow] = av0.w;
        As[ak + 4][arow] = av1.x; As[ak + 5][arow] = av1.y;
        As[ak + 6][arow] = av1.z; As[ak + 7][arow] = av1.w;
        Bth[brow][0 * 16 + bq] = bh0.x; Bth[brow][1 * 16 + bq] = bh0.y;
        Bth[brow][2 * 16 + bq] = bh0.z; Bth[brow][3 * 16 + bq] = bh0.w;
        Bth[brow][4 * 16 + bq] = bh1.x; Bth[brow][5 * 16 + bq] = bh1.y;
        Bth[brow][6 * 16 + bq] = bh1.z; Bth[brow][7 * 16 + bq] = bh1.w;
        Btl[brow][0 * 16 + bq] = bl0.x; Btl[brow][1 * 16 + bq] = bl0.y;
        Btl[brow][2 * 16 + bq] = bl0.z; Btl[brow][3 * 16 + bq] = bl0.w;
        Btl[brow][4 * 16 + bq] = bl1.x; Btl[brow][5 * 16 + bq] = bl1.y;
        Btl[brow][6 * 16 + bq] = bl1.z; Btl[brow][7 * 16 + bq] = bl1.w;
        __syncthreads();
        #pragma unroll
        for (int kc = 0; kc < 16; kc += 8) {
            // A fragment: rows m = wid*16 + gid (+8); cols kc+tg (+4)
            float a0f = As[kc + tg][wid * 16 + gid];
            float a1f = As[kc + tg][wid * 16 + gid + 8];
            float a2f = As[kc + tg + 4][wid * 16 + gid];
            float a3f = As[kc + tg + 4][wid * 16 + gid + 8];
            uint32_t ahi[4], alo[4];
            ahi[0] = tf32_of(a0f); alo[0] = tf32_of(a0f - __uint_as_float(ahi[0]));
            ahi[1] = tf32_of(a1f); alo[1] = tf32_of(a1f - __uint_as_float(ahi[1]));
            ahi[2] = tf32_of(a2f); alo[2] = tf32_of(a2f - __uint_as_float(ahi[2]));
            ahi[3] = tf32_of(a3f); alo[3] = tf32_of(a3f - __uint_as_float(ahi[3]));
            #pragma unroll
            for (int tgrp = 0; tgrp < 4; tgrp++) {
                float4 h0 = *(const float4*)&Bth[kc + tg][gid * 16 + tgrp * 4];
                float4 h1 = *(const float4*)&Bth[kc + tg + 4][gid * 16 + tgrp * 4];
                float4 l0 = *(const float4*)&Btl[kc + tg][gid * 16 + tgrp * 4];
                float4 l1 = *(const float4*)&Btl[kc + tg + 4][gid * 16 + tgrp * 4];
                float* ac0 = acc[tgrp * 4 + 0];
                float* ac1 = acc[tgrp * 4 + 1];
                float* ac2 = acc[tgrp * 4 + 2];
                float* ac3 = acc[tgrp * 4 + 3];
                mma_tf32(ac0, ahi, h0.x, h1.x); mma_tf32(ac0, alo, h0.x, h1.x);
                mma_tf32(ac0, ahi, l0.x, l1.x);
                mma_tf32(ac1, ahi, h0.y, h1.y); mma_tf32(ac1, alo, h0.y, h1.y);
                mma_tf32(ac1, ahi, l0.y, l1.y);
                mma_tf32(ac2, ahi, h0.z, h1.z); mma_tf32(ac2, alo, h0.z, h1.z);
                mma_tf32(ac2, ahi, l0.z, l1.z);
                mma_tf32(ac3, ahi, h0.w, h1.w); mma_tf32(ac3, alo, h0.w, h1.w);
                mma_tf32(ac3, ahi, l0.w, l1.w);
            }
        }
    }

    // epilogue: c0,c1 -> (row m0+wid*16+gid, cols t*8+tg*2, +1); c2,c3 -> row +8
    int r0 = m0 + wid * 16 + gid;
    int r1 = r0 + 8;
    #pragma unroll
    for (int t = 0; t < 16; t++) {
        int c = t * 8 + tg * 2;
        float v0 = acc[t][0], v1 = acc[t][1], v2 = acc[t][2], v3 = acc[t][3];
        if (MODE == 0) {
            float bb0 = bias[c], bb1 = bias[c + 1];
            v0 = fmaxf(v0 + bb0, 0.f); v1 = fmaxf(v1 + bb1, 0.f);
            v2 = fmaxf(v2 + bb0, 0.f); v3 = fmaxf(v3 + bb1, 0.f);
        }
        if (r0 < N_NODES) *(float2*)&C[(size_t)r0 * 128 + c] = make_float2(v0, v1);
        if (r1 < N_NODES) *(float2*)&C[(size_t)r1 * 128 + c] = make_float2(v2, v3);
    }
}

// ---------------- gather-side aggregation, layer 2 (+ fused final) ----------------
__global__ __launch_bounds__(256) void k_agg2(const float* __restrict__ b2) {
    int gt = blockIdx.x * blockDim.x + threadIdx.x;
    int w = gt >> 5, lane = gt & 31;
    if (w >= N_NODES) return;
    int start = g_rowptr[w], end = g_rowptr[w + 1];
    float ax = 0.f, ay = 0.f;
    const float2* uv2 = (const float2*)g_uv;
    for (int i = start; i < end; i += 32) {
        int m = min(32, end - i);
        int eid = (i + lane < end) ? g_csr[i + lane] : 0;
        for (int j = 0; j < m; j++) {
            int s = __shfl_sync(0xffffffffu, eid, j);
            float2 v = __ldg(uv2 + (size_t)s * 64 + lane);
            ax += v.x; ay += v.y;
        }
    }
    float di = g_deginv[w];
    float rx = g_uv[(size_t)w * 128 + 64 + lane * 2];
    float ry = g_uv[(size_t)w * 128 + 64 + lane * 2 + 1];
    g_h2[(size_t)w * 64 + lane * 2]     = rx + ax * di + b2[lane * 2];
    g_h2[(size_t)w * 64 + lane * 2 + 1] = ry + ay * di + b2[lane * 2 + 1];
}

// ---------------- edge dot via CSR: warp per dst, 8 lanes/edge, 4 edges/iter ----
__global__ __launch_bounds__(256) void k_edge3(float* __restrict__ out) {
    int gt = blockIdx.x * blockDim.x + threadIdx.x;
    int w = gt >> 5, lane = gt & 31;
    if (w >= N_NODES) return;
    int g = lane >> 3;
    int k = lane & 7;
    const float4* h4 = (const float4*)g_h2;
    float4 d0 = h4[(size_t)w * 16 + k * 2];
    float4 d1 = h4[(size_t)w * 16 + k * 2 + 1];
    int start = g_rowptr[w], end = g_rowptr[w + 1];
    for (int i = start; i < end; i += 4) {
        int idx = i + g;
        bool valid = idx < end;
        int s = 0, eid = 0;
        if (valid) { s = g_csr[idx]; eid = g_eid[idx]; }
        float acc = 0.f;
        if (valid) {
            float4 a0 = __ldg(&h4[(size_t)s * 16 + k * 2]);
            float4 a1 = __ldg(&h4[(size_t)s * 16 + k * 2 + 1]);
            acc = a0.x * d0.x + a0.y * d0.y + a0.z * d0.z + a0.w * d0.w
                + a1.x * d1.x + a1.y * d1.y + a1.z * d1.z + a1.w * d1.w;
        }
        acc += __shfl_xor_sync(0xffffffffu, acc, 1);
        acc += __shfl_xor_sync(0xffffffffu, acc, 2);
        acc += __shfl_xor_sync(0xffffffffu, acc, 4);
        if (valid && k == 0) out[eid] = acc;
    }
}

// ---------------- launch ----------------
extern "C" void kernel_launch(void* const* d_in, const int* in_sizes, int n_in,
                              void* d_out, int out_size) {
    const float* x   = (const float*)d_in[0];
    const float* pos = (const float*)d_in[1];
    const int*   ei  = (const int*)d_in[2];
    const float* W1r = (const float*)d_in[3];
    const float* W1n = (const float*)d_in[4];
    const float* b1  = (const float*)d_in[5];
    const float* W2r = (const float*)d_in[6];
    const float* W2n = (const float*)d_in[7];
    const float* b2  = (const float*)d_in[8];
    float* out = (float*)d_out;

    int E = in_sizes[2] / 2;
    const int* src = ei;
    const int* dst = ei + E;

    k_prepw<<<160, 256>>>(W1r, W1n, W2r, W2n);
    k_deg<<<(E + 255) / 256, 256>>>(dst, E);
    k_scan1<<<NB, SB>>>();
    k_scan2<<<1, 32>>>();
    k_scan3<<<(N_NODES + 255) / 256, 256>>>(E);
    k_fillcsr<<<(E + 255) / 256, 256>>>(src, dst, E);
    k_buildA1<<<(N_NODES * 68 + 255) / 256, 256>>>(x, pos);
    k_agg1<<<(N_NODES * 32 + 255) / 256, 256>>>(x, pos);
    k_gemm_tc<0><<<GBLK_TC, 256>>>(b1);
    k_gemm_tc<1><<<GBLK_TC, 256>>>(b1);
    k_agg2<<<(N_NODES * 32 + 255) / 256, 256>>>(b2);
    k_edge3<<<(N_NODES * 32 + 255) / 256, 256>>>(out);
}

// round 13
// speedup vs baseline: 1.0421x; 1.0421x over previous
#include <cuda_runtime.h>
#include <cstdint>

#define N_NODES 50000
#define EMAX 1600000
#define LDA 144
#define SB 512
#define NB 98            // ceil(N_NODES/512)
#define GBLK_TC 391      // ceil(N_NODES/128)

// ---------------- scratch (static __device__, no allocation) ----------------
__device__ float g_A[N_NODES * LDA];      // layer-1 GEMM input, stride 144 (cols 134..143 stay 0)
__device__ float g_h1[N_NODES * 128];     // relu output layer 1
__device__ float g_uv[N_NODES * 128];     // cols 0..63 = h1@W2_nbr, cols 64..127 = h1@W2_root
__device__ float g_h2[N_NODES * 64];      // final embeddings
__device__ float g_deginv[N_NODES];
__device__ int   g_deg[N_NODES];
__device__ int   g_cur[N_NODES];
__device__ int   g_rowptr[N_NODES + 1];
__device__ int   g_bsum[NB];
__device__ int   g_boff[NB];
__device__ int   g_csr[EMAX];             // src ids bucketed by dst
__device__ int   g_eid[EMAX];             // original edge id bucketed by dst
// bf16x2-packed weight k-pairs: [kpair][n], lo half = even k, hi half = odd k
__device__ uint32_t g_W1h2[72 * 128];
__device__ uint32_t g_W1l2[72 * 128];
__device__ uint32_t g_W2h2[64 * 128];
__device__ uint32_t g_W2l2[64 * 128];

// ---------------- bf16 helpers ----------------
__device__ __forceinline__ uint32_t bf2_of(float odd, float even) {
    // d.hi = bf16(odd), d.lo = bf16(even)
    uint32_t r; asm("cvt.rn.bf16x2.f32 %0, %1, %2;" : "=r"(r) : "f"(odd), "f"(even));
    return r;
}
__device__ __forceinline__ void split_pair(float e, float o, uint32_t &hi, uint32_t &lo) {
    hi = bf2_of(o, e);
    float ef = __uint_as_float(hi << 16);
    float of = __uint_as_float(hi & 0xffff0000u);
    lo = bf2_of(o - of, e - ef);
}
__device__ __forceinline__ void mma_bf16(float* c, const uint32_t* a, uint32_t b0, uint32_t b1) {
    asm volatile(
        "mma.sync.aligned.m16n8k16.row.col.f32.bf16.bf16.f32 "
        "{%0,%1,%2,%3}, {%4,%5,%6,%7}, {%8,%9}, {%0,%1,%2,%3};"
        : "+f"(c[0]), "+f"(c[1]), "+f"(c[2]), "+f"(c[3])
        : "r"(a[0]), "r"(a[1]), "r"(a[2]), "r"(a[3]), "r"(b0), "r"(b1));
}

// ---------------- fused prep: zero counters + split weights + build A cols 0..67 ----
__global__ void k_prepw(const float* __restrict__ W1r, const float* __restrict__ W1n,
                        const float* __restrict__ W2r, const float* __restrict__ W2n,
                        const float* __restrict__ x,   const float* __restrict__ pos) {
    int t0 = blockIdx.x * blockDim.x + threadIdx.x;
    int stride = gridDim.x * blockDim.x;
    for (int i = t0; i < N_NODES; i += stride) { g_deg[i] = 0; g_cur[i] = 0; }
    // W1 combined [144,128]: rows 0-65 W1r, 68-133 W1n, rest 0 -> 72 k-pairs
    for (int i = t0; i < 72 * 128; i += stride) {
        int kp = i >> 7, n = i & 127;
        int r0 = 2 * kp, r1 = 2 * kp + 1;
        float we = 0.f, wo = 0.f;
        if (r0 < 66) we = W1r[r0 * 128 + n];
        else if (r0 >= 68 && r0 < 134) we = W1n[(r0 - 68) * 128 + n];
        if (r1 < 66) wo = W1r[r1 * 128 + n];
        else if (r1 >= 68 && r1 < 134) wo = W1n[(r1 - 68) * 128 + n];
        uint32_t hi, lo;
        split_pair(we, wo, hi, lo);
        g_W1h2[i] = hi; g_W1l2[i] = lo;
    }
    // W2 combined [128,128]: cols 0-63 W2n, 64-127 W2r -> 64 k-pairs
    for (int i = t0; i < 64 * 128; i += stride) {
        int kp = i >> 7, n = i & 127;
        int r0 = 2 * kp, r1 = 2 * kp + 1;
        float we = (n < 64) ? W2n[r0 * 64 + n] : W2r[r0 * 64 + (n - 64)];
        float wo = (n < 64) ? W2n[r1 * 64 + n] : W2r[r1 * 64 + (n - 64)];
        uint32_t hi, lo;
        split_pair(we, wo, hi, lo);
        g_W2h2[i] = hi; g_W2l2[i] = lo;
    }
    // A cols 0..67 = concat(x, pos)
    for (int i = t0; i < N_NODES * 68; i += stride) {
        int n = i / 68, c = i % 68;
        float v = 0.0f;
        if (c < 64) v = x[n * 64 + c];
        else if (c < 66) v = pos[n * 2 + (c - 64)];
        g_A[(size_t)n * LDA + c] = v;
    }
}

__global__ void k_deg(const int* __restrict__ dst, int E) {
    int i = blockIdx.x * blockDim.x + threadIdx.x;
    if (i < E) atomicAdd(&g_deg[dst[i]], 1);
}

__global__ void k_scan1() {
    __shared__ int s[SB];
    int tid = threadIdx.x;
    int i = blockIdx.x * SB + tid;
    int v = (i < N_NODES) ? g_deg[i] : 0;
    s[tid] = v;
    __syncthreads();
    #pragma unroll
    for (int off = 1; off < SB; off <<= 1) {
        int t = (tid >= off) ? s[tid - off] : 0;
        __syncthreads();
        s[tid] += t;
        __syncthreads();
    }
    if (i < N_NODES) g_rowptr[i] = s[tid] - v;
    if (tid == SB - 1) g_bsum[blockIdx.x] = s[tid];
}

// warp-parallel scan of NB block sums
__global__ void k_scan2() {
    int lane = threadIdx.x;
    int run = 0;
    for (int base = 0; base < NB; base += 32) {
        int idx = base + lane;
        int v = (idx < NB) ? g_bsum[idx] : 0;
        int s = v;
        #pragma unroll
        for (int off = 1; off < 32; off <<= 1) {
            int t = __shfl_up_sync(0xffffffffu, s, off);
            if (lane >= off) s += t;
        }
        if (idx < NB) g_boff[idx] = run + s - v;
        run += __shfl_sync(0xffffffffu, s, 31);
    }
}

__global__ void k_scan3(int E) {
    int i = blockIdx.x * blockDim.x + threadIdx.x;
    if (i < N_NODES) {
        g_rowptr[i] += g_boff[i / SB];
        g_deginv[i] = 1.0f / fmaxf((float)g_deg[i], 1.0f);
    }
    if (i == 0) g_rowptr[N_NODES] = E;
}

__global__ void k_fillcsr(const int* __restrict__ src, const int* __restrict__ dst, int E) {
    int e = blockIdx.x * blockDim.x + threadIdx.x;
    if (e >= E) return;
    int d = dst[e];
    int ofs = atomicAdd(&g_cur[d], 1);
    int pos = g_rowptr[d] + ofs;
    g_csr[pos] = src[e];
    g_eid[pos] = e;
}

// ---------------- gather-side aggregation, layer 1 ----------------
__global__ __launch_bounds__(256) void k_agg1(const float* __restrict__ x,
                                              const float* __restrict__ pos) {
    int gt = blockIdx.x * blockDim.x + threadIdx.x;
    int w = gt >> 5, lane = gt & 31;
    if (w >= N_NODES) return;
    int start = g_rowptr[w], end = g_rowptr[w + 1];
    float ax = 0.f, ay = 0.f, px = 0.f, py = 0.f;
    const float2* x2 = (const float2*)x;
    const float2* p2 = (const float2*)pos;
    for (int i = start; i < end; i += 32) {
        int m = min(32, end - i);
        int eid = (i + lane < end) ? g_csr[i + lane] : 0;
        for (int j = 0; j < m; j++) {
            int s = __shfl_sync(0xffffffffu, eid, j);
            float2 v = __ldg(x2 + (size_t)s * 32 + lane);
            ax += v.x; ay += v.y;
            if (lane == 0) { float2 p = __ldg(p2 + s); px += p.x; py += p.y; }
        }
    }
    float di = g_deginv[w];
    float* rowp = g_A + (size_t)w * LDA;
    rowp[68 + lane * 2]     = ax * di;
    rowp[68 + lane * 2 + 1] = ay * di;
    if (lane == 0) { rowp[132] = px * di; rowp[133] = py * di; }
}

// ---------------- bf16 tensor-core GEMM: C[M,128] = A[M,K] @ B[K,128] ----------------
// mma.m16n8k16 bf16, 3-term split (Ah*Bh + Al*Bh + Ah*Bl), fp32 accumulate.
// 128x128 block tile, 8 warps; warp w: rows w*16..+16, 16 n-tiles.
template <int MODE>
__global__ __launch_bounds__(256) void k_gemm_bf(const float* __restrict__ bias) {
    const int KP  = (MODE == 0) ? 72 : 64;    // k-pairs
    const int lda = (MODE == 0) ? 144 : 128;
    const float* __restrict__ A = (MODE == 0) ? g_A : g_h1;
    const uint32_t* __restrict__ BH = (MODE == 0) ? g_W1h2 : g_W2h2;
    const uint32_t* __restrict__ BL = (MODE == 0) ? g_W1l2 : g_W2l2;
    float* __restrict__ C = (MODE == 0) ? g_h1 : g_uv;

    __shared__ float    As[16][132];    // [k][m], fragment rows 2tg -> banks 8tg+gid (clean)
    __shared__ uint32_t Bsh[8][136];    // [kpair][n], banks tg*8+gid (clean)
    __shared__ uint32_t Bsl[8][136];

    int tid  = threadIdx.x;
    int wid  = tid >> 5, lane = tid & 31;
    int tg   = lane & 3, gid = lane >> 2;
    int m0   = blockIdx.x * 128;
    int mrow = wid * 16 + gid;

    int arow = tid >> 1;
    int ak   = (tid & 1) * 8;
    int a_grow = min(m0 + arow, N_NODES - 1);
    int brow = tid >> 5;                // 0..7
    int bcol = (tid & 31) * 4;          // 0..124

    float acc[16][4];
    #pragma unroll
    for (int t = 0; t < 16; t++)
        #pragma unroll
        for (int i = 0; i < 4; i++) acc[t][i] = 0.0f;

    for (int kp0 = 0; kp0 < KP; kp0 += 8) {
        int k0 = kp0 * 2;
        float4 av0 = *(const float4*)(A + (size_t)a_grow * lda + k0 + ak);
        float4 av1 = *(const float4*)(A + (size_t)a_grow * lda + k0 + ak + 4);
        uint4 bh4 = *(const uint4*)(BH + (size_t)(kp0 + brow) * 128 + bcol);
        uint4 bl4 = *(const uint4*)(BL + (size_t)(kp0 + brow) * 128 + bcol);
        __syncthreads();
        As[ak + 0][arow] = av0.x; As[ak + 1][arow] = av0.y;
        As[ak + 2][arow] = av0.z; As[ak + 3][arow] = av0.w;
        As[ak + 4][arow] = av1.x; As[ak + 5][arow] = av1.y;
        As[ak + 6][arow] = av1.z; As[ak + 7][arow] = av1.w;
        *(uint4*)&Bsh[brow][bcol] = bh4;
        *(uint4*)&Bsl[brow][bcol] = bl4;
        __syncthreads();

        // A fragments: rows mrow, mrow+8; k pairs (2tg,2tg+1) and (2tg+8,2tg+9)
        float ae0 = As[2 * tg][mrow],     ao0 = As[2 * tg + 1][mrow];
        float ae1 = As[2 * tg][mrow + 8], ao1 = As[2 * tg + 1][mrow + 8];
        float ae2 = As[2 * tg + 8][mrow],     ao2 = As[2 * tg + 9][mrow];
        float ae3 = As[2 * tg + 8][mrow + 8], ao3 = As[2 * tg + 9][mrow + 8];
        uint32_t ah[4], al[4];
        split_pair(ae0, ao0, ah[0], al[0]);
        split_pair(ae1, ao1, ah[1], al[1]);
        split_pair(ae2, ao2, ah[2], al[2]);
        split_pair(ae3, ao3, ah[3], al[3]);

        #pragma unroll
        for (int t = 0; t < 16; t++) {
            int n = t * 8 + gid;
            uint32_t bh0 = Bsh[tg][n],     bh1 = Bsh[tg + 4][n];
            uint32_t bl0 = Bsl[tg][n],     bl1 = Bsl[tg + 4][n];
            mma_bf16(acc[t], ah, bh0, bh1);
            mma_bf16(acc[t], al, bh0, bh1);
            mma_bf16(acc[t], ah, bl0, bl1);
        }
    }

    // epilogue: c0,c1 -> (row m0+wid*16+gid, cols t*8+tg*2, +1); c2,c3 -> row +8
    int r0 = m0 + wid * 16 + gid;
    int r1 = r0 + 8;
    #pragma unroll
    for (int t = 0; t < 16; t++) {
        int c = t * 8 + tg * 2;
        float v0 = acc[t][0], v1 = acc[t][1], v2 = acc[t][2], v3 = acc[t][3];
        if (MODE == 0) {
            float bb0 = bias[c], bb1 = bias[c + 1];
            v0 = fmaxf(v0 + bb0, 0.f); v1 = fmaxf(v1 + bb1, 0.f);
            v2 = fmaxf(v2 + bb0, 0.f); v3 = fmaxf(v3 + bb1, 0.f);
        }
        if (r0 < N_NODES) *(float2*)&C[(size_t)r0 * 128 + c] = make_float2(v0, v1);
        if (r1 < N_NODES) *(float2*)&C[(size_t)r1 * 128 + c] = make_float2(v2, v3);
    }
}

// ---------------- gather-side aggregation, layer 2 (+ fused final) ----------------
__global__ __launch_bounds__(256) void k_agg2(const float* __restrict__ b2) {
    int gt = blockIdx.x * blockDim.x + threadIdx.x;
    int w = gt >> 5, lane = gt & 31;
    if (w >= N_NODES) return;
    int start = g_rowptr[w], end = g_rowptr[w + 1];
    float ax = 0.f, ay = 0.f;
    const float2* uv2 = (const float2*)g_uv;
    for (int i = start; i < end; i += 32) {
        int m = min(32, end - i);
        int eid = (i + lane < end) ? g_csr[i + lane] : 0;
        for (int j = 0; j < m; j++) {
            int s = __shfl_sync(0xffffffffu, eid, j);
            float2 v = __ldg(uv2 + (size_t)s * 64 + lane);
            ax += v.x; ay += v.y;
        }
    }
    float di = g_deginv[w];
    float rx = g_uv[(size_t)w * 128 + 64 + lane * 2];
    float ry = g_uv[(size_t)w * 128 + 64 + lane * 2 + 1];
    g_h2[(size_t)w * 64 + lane * 2]     = rx + ax * di + b2[lane * 2];
    g_h2[(size_t)w * 64 + lane * 2 + 1] = ry + ay * di + b2[lane * 2 + 1];
}

// ---------------- edge dot via CSR: warp per dst, 8 lanes/edge, 4 edges/iter ----
__global__ __launch_bounds__(256) void k_edge3(float* __restrict__ out) {
    int gt = blockIdx.x * blockDim.x + threadIdx.x;
    int w = gt >> 5, lane = gt & 31;
    if (w >= N_NODES) return;
    int g = lane >> 3;
    int k = lane & 7;
    const float4* h4 = (const float4*)g_h2;
    float4 d0 = h4[(size_t)w * 16 + k * 2];
    float4 d1 = h4[(size_t)w * 16 + k * 2 + 1];
    int start = g_rowptr[w], end = g_rowptr[w + 1];
    for (int i = start; i < end; i += 4) {
        int idx = i + g;
        bool valid = idx < end;
        int s = 0, eid = 0;
        if (valid) { s = g_csr[idx]; eid = g_eid[idx]; }
        float acc = 0.f;
        if (valid) {
            float4 a0 = __ldg(&h4[(size_t)s * 16 + k * 2]);
            float4 a1 = __ldg(&h4[(size_t)s * 16 + k * 2 + 1]);
            acc = a0.x * d0.x + a0.y * d0.y + a0.z * d0.z + a0.w * d0.w
                + a1.x * d1.x + a1.y * d1.y + a1.z * d1.z + a1.w * d1.w;
        }
        acc += __shfl_xor_sync(0xffffffffu, acc, 1);
        acc += __shfl_xor_sync(0xffffffffu, acc, 2);
        acc += __shfl_xor_sync(0xffffffffu, acc, 4);
        if (valid && k == 0) out[eid] = acc;
    }
}

// ---------------- launch ----------------
extern "C" void kernel_launch(void* const* d_in, const int* in_sizes, int n_in,
                              void* d_out, int out_size) {
    const float* x   = (const float*)d_in[0];
    const float* pos = (const float*)d_in[1];
    const int*   ei  = (const int*)d_in[2];
    const float* W1r = (const float*)d_in[3];
    const float* W1n = (const float*)d_in[4];
    const float* b1  = (const float*)d_in[5];
    const float* W2r = (const float*)d_in[6];
    const float* W2n = (const float*)d_in[7];
    const float* b2  = (const float*)d_in[8];
    float* out = (float*)d_out;

    int E = in_sizes[2] / 2;
    const int* src = ei;
    const int* dst = ei + E;

    k_prepw<<<256, 256>>>(W1r, W1n, W2r, W2n, x, pos);
    k_deg<<<(E + 255) / 256, 256>>>(dst, E);
    k_scan1<<<NB, SB>>>();
    k_scan2<<<1, 32>>>();
    k_scan3<<<(N_NODES + 255) / 256, 256>>>(E);
    k_fillcsr<<<(E + 255) / 256, 256>>>(src, dst, E);
    k_agg1<<<(N_NODES * 32 + 255) / 256, 256>>>(x, pos);
    k_gemm_bf<0><<<GBLK_TC, 256>>>(b1);
    k_gemm_bf<1><<<GBLK_TC, 256>>>(b1);
    k_agg2<<<(N_NODES * 32 + 255) / 256, 256>>>(b2);
    k_edge3<<<(N_NODES * 32 + 255) / 256, 256>>>(out);
}

// round 14
// speedup vs baseline: 1.0941x; 1.0499x over previous
#include <cuda_runtime.h>
#include <cstdint>

#define N_NODES 50000
#define EMAX 1600000
#define LDA 144
#define GBLK_TC 391      // ceil(N_NODES/128)

// ---------------- scratch (static __device__, no allocation) ----------------
__device__ float    g_A[N_NODES * LDA];   // layer-1 GEMM input, stride 144
__device__ float    g_h1[N_NODES * 128];  // relu output layer 1
__device__ uint32_t g_ub[N_NODES * 32];   // u = h1@W2_nbr as bf16x2 (64 bf16/row)
__device__ float    g_ur[N_NODES * 64];   // r = h1@W2_root fp32
__device__ uint32_t g_h2b[N_NODES * 32];  // final embeddings bf16x2 (64 bf16/row)
__device__ float    g_deginv[N_NODES];
__device__ int      g_deg[N_NODES];
__device__ int      g_cur[N_NODES];
__device__ int      g_rowptr[N_NODES];
__device__ int      g_total;
__device__ int      g_csr[EMAX];          // src ids bucketed by dst
__device__ int      g_eid[EMAX];          // original edge id bucketed by dst
// bf16x2-packed weight k-pairs: [kpair][n], lo half = even k, hi half = odd k
__device__ uint32_t g_W1h2[72 * 128];
__device__ uint32_t g_W1l2[72 * 128];
__device__ uint32_t g_W2h2[64 * 128];
__device__ uint32_t g_W2l2[64 * 128];

// ---------------- bf16 helpers ----------------
__device__ __forceinline__ uint32_t bf2_of(float odd, float even) {
    // d.hi = bf16(odd), d.lo = bf16(even)
    uint32_t r; asm("cvt.rn.bf16x2.f32 %0, %1, %2;" : "=r"(r) : "f"(odd), "f"(even));
    return r;
}
__device__ __forceinline__ float2 bf2f(uint32_t u) {
    float2 r;
    r.x = __uint_as_float(u << 16);
    r.y = __uint_as_float(u & 0xffff0000u);
    return r;
}
__device__ __forceinline__ void split_pair(float e, float o, uint32_t &hi, uint32_t &lo) {
    hi = bf2_of(o, e);
    float ef = __uint_as_float(hi << 16);
    float of = __uint_as_float(hi & 0xffff0000u);
    lo = bf2_of(o - of, e - ef);
}
__device__ __forceinline__ void mma_bf16(float* c, const uint32_t* a, uint32_t b0, uint32_t b1) {
    asm volatile(
        "mma.sync.aligned.m16n8k16.row.col.f32.bf16.bf16.f32 "
        "{%0,%1,%2,%3}, {%4,%5,%6,%7}, {%8,%9}, {%0,%1,%2,%3};"
        : "+f"(c[0]), "+f"(c[1]), "+f"(c[2]), "+f"(c[3])
        : "r"(a[0]), "r"(a[1]), "r"(a[2]), "r"(a[3]), "r"(b0), "r"(b1));
}

// ---------------- fused prep: zero counters + split weights + build A cols 0..67 ----
__global__ void k_prepw(const float* __restrict__ W1r, const float* __restrict__ W1n,
                        const float* __restrict__ W2r, const float* __restrict__ W2n,
                        const float* __restrict__ x,   const float* __restrict__ pos) {
    int t0 = blockIdx.x * blockDim.x + threadIdx.x;
    int stride = gridDim.x * blockDim.x;
    if (t0 == 0) g_total = 0;
    for (int i = t0; i < N_NODES; i += stride) { g_deg[i] = 0; g_cur[i] = 0; }
    for (int i = t0; i < 72 * 128; i += stride) {
        int kp = i >> 7, n = i & 127;
        int r0 = 2 * kp, r1 = 2 * kp + 1;
        float we = 0.f, wo = 0.f;
        if (r0 < 66) we = W1r[r0 * 128 + n];
        else if (r0 >= 68 && r0 < 134) we = W1n[(r0 - 68) * 128 + n];
        if (r1 < 66) wo = W1r[r1 * 128 + n];
        else if (r1 >= 68 && r1 < 134) wo = W1n[(r1 - 68) * 128 + n];
        uint32_t hi, lo;
        split_pair(we, wo, hi, lo);
        g_W1h2[i] = hi; g_W1l2[i] = lo;
    }
    for (int i = t0; i < 64 * 128; i += stride) {
        int kp = i >> 7, n = i & 127;
        int r0 = 2 * kp, r1 = 2 * kp + 1;
        float we = (n < 64) ? W2n[r0 * 64 + n] : W2r[r0 * 64 + (n - 64)];
        float wo = (n < 64) ? W2n[r1 * 64 + n] : W2r[r1 * 64 + (n - 64)];
        uint32_t hi, lo;
        split_pair(we, wo, hi, lo);
        g_W2h2[i] = hi; g_W2l2[i] = lo;
    }
    for (int i = t0; i < N_NODES * 68; i += stride) {
        int n = i / 68, c = i % 68;
        float v = 0.0f;
        if (c < 64) v = x[n * 64 + c];
        else if (c < 66) v = pos[n * 2 + (c - 64)];
        g_A[(size_t)n * LDA + c] = v;
    }
}

__global__ void k_deg(const int* __restrict__ dst, int E) {
    int i = blockIdx.x * blockDim.x + threadIdx.x;
    if (i < E) atomicAdd(&g_deg[dst[i]], 1);
}

// CSR bucket bases via warp-aggregated atomic on a global cursor (order-free).
__global__ void k_base() {
    int i = blockIdx.x * blockDim.x + threadIdx.x;
    int lane = threadIdx.x & 31;
    int d = (i < N_NODES) ? g_deg[i] : 0;
    int s = d;
    #pragma unroll
    for (int off = 1; off < 32; off <<= 1) {
        int t = __shfl_up_sync(0xffffffffu, s, off);
        if (lane >= off) s += t;
    }
    int base = 0;
    if (lane == 31) base = atomicAdd(&g_total, s);
    base = __shfl_sync(0xffffffffu, base, 31);
    if (i < N_NODES) {
        g_rowptr[i] = base + s - d;
        g_deginv[i] = 1.0f / fmaxf((float)d, 1.0f);
    }
}

__global__ void k_fillcsr(const int* __restrict__ src, const int* __restrict__ dst, int E) {
    int e = blockIdx.x * blockDim.x + threadIdx.x;
    if (e >= E) return;
    int d = dst[e];
    int ofs = atomicAdd(&g_cur[d], 1);
    int pos = g_rowptr[d] + ofs;
    g_csr[pos] = src[e];
    g_eid[pos] = e;
}

// ---------------- gather-side aggregation, layer 1 (fp32 path, exact) ----------------
__global__ __launch_bounds__(256) void k_agg1(const float* __restrict__ x,
                                              const float* __restrict__ pos) {
    int gt = blockIdx.x * blockDim.x + threadIdx.x;
    int w = gt >> 5, lane = gt & 31;
    if (w >= N_NODES) return;
    int start = g_rowptr[w], end = start + g_deg[w];
    float ax = 0.f, ay = 0.f, px = 0.f, py = 0.f;
    const float2* x2 = (const float2*)x;
    const float2* p2 = (const float2*)pos;
    for (int i = start; i < end; i += 32) {
        int m = min(32, end - i);
        int eid = (i + lane < end) ? g_csr[i + lane] : 0;
        for (int j = 0; j < m; j++) {
            int s = __shfl_sync(0xffffffffu, eid, j);
            float2 v = __ldg(x2 + (size_t)s * 32 + lane);
            ax += v.x; ay += v.y;
            if (lane == 0) { float2 p = __ldg(p2 + s); px += p.x; py += p.y; }
        }
    }
    float di = g_deginv[w];
    float* rowp = g_A + (size_t)w * LDA;
    rowp[68 + lane * 2]     = ax * di;
    rowp[68 + lane * 2 + 1] = ay * di;
    if (lane == 0) { rowp[132] = px * di; rowp[133] = py * di; }
}

// ---------------- bf16 tensor-core GEMM: C[M,128] = A[M,K] @ B[K,128] ----------------
// mma.m16n8k16 bf16, 3-term split. MODE 0 -> g_h1 (bias+relu). MODE 1 -> g_ub/g_ur.
template <int MODE>
__global__ __launch_bounds__(256) void k_gemm_bf(const float* __restrict__ bias) {
    const int KP  = (MODE == 0) ? 72 : 64;    // k-pairs
    const int lda = (MODE == 0) ? 144 : 128;
    const float* __restrict__ A = (MODE == 0) ? g_A : g_h1;
    const uint32_t* __restrict__ BH = (MODE == 0) ? g_W1h2 : g_W2h2;
    const uint32_t* __restrict__ BL = (MODE == 0) ? g_W1l2 : g_W2l2;

    __shared__ float    As[16][132];
    __shared__ uint32_t Bsh[8][136];
    __shared__ uint32_t Bsl[8][136];

    int tid  = threadIdx.x;
    int wid  = tid >> 5, lane = tid & 31;
    int tg   = lane & 3, gid = lane >> 2;
    int m0   = blockIdx.x * 128;
    int mrow = wid * 16 + gid;

    int arow = tid >> 1;
    int ak   = (tid & 1) * 8;
    int a_grow = min(m0 + arow, N_NODES - 1);
    int brow = tid >> 5;
    int bcol = (tid & 31) * 4;

    float acc[16][4];
    #pragma unroll
    for (int t = 0; t < 16; t++)
        #pragma unroll
        for (int i = 0; i < 4; i++) acc[t][i] = 0.0f;

    for (int kp0 = 0; kp0 < KP; kp0 += 8) {
        int k0 = kp0 * 2;
        float4 av0 = *(const float4*)(A + (size_t)a_grow * lda + k0 + ak);
        float4 av1 = *(const float4*)(A + (size_t)a_grow * lda + k0 + ak + 4);
        uint4 bh4 = *(const uint4*)(BH + (size_t)(kp0 + brow) * 128 + bcol);
        uint4 bl4 = *(const uint4*)(BL + (size_t)(kp0 + brow) * 128 + bcol);
        __syncthreads();
        As[ak + 0][arow] = av0.x; As[ak + 1][arow] = av0.y;
        As[ak + 2][arow] = av0.z; As[ak + 3][arow] = av0.w;
        As[ak + 4][arow] = av1.x; As[ak + 5][arow] = av1.y;
        As[ak + 6][arow] = av1.z; As[ak + 7][arow] = av1.w;
        *(uint4*)&Bsh[brow][bcol] = bh4;
        *(uint4*)&Bsl[brow][bcol] = bl4;
        __syncthreads();

        float ae0 = As[2 * tg][mrow],     ao0 = As[2 * tg + 1][mrow];
        float ae1 = As[2 * tg][mrow + 8], ao1 = As[2 * tg + 1][mrow + 8];
        float ae2 = As[2 * tg + 8][mrow],     ao2 = As[2 * tg + 9][mrow];
        float ae3 = As[2 * tg + 8][mrow + 8], ao3 = As[2 * tg + 9][mrow + 8];
        uint32_t ah[4], al[4];
        split_pair(ae0, ao0, ah[0], al[0]);
        split_pair(ae1, ao1, ah[1], al[1]);
        split_pair(ae2, ao2, ah[2], al[2]);
        split_pair(ae3, ao3, ah[3], al[3]);

        #pragma unroll
        for (int t = 0; t < 16; t++) {
            int n = t * 8 + gid;
            uint32_t bh0 = Bsh[tg][n], bh1 = Bsh[tg + 4][n];
            uint32_t bl0 = Bsl[tg][n], bl1 = Bsl[tg + 4][n];
            mma_bf16(acc[t], ah, bh0, bh1);
            mma_bf16(acc[t], al, bh0, bh1);
            mma_bf16(acc[t], ah, bl0, bl1);
        }
    }

    int r0 = m0 + wid * 16 + gid;
    int r1 = r0 + 8;
    #pragma unroll
    for (int t = 0; t < 16; t++) {
        int c = t * 8 + tg * 2;
        float v0 = acc[t][0], v1 = acc[t][1], v2 = acc[t][2], v3 = acc[t][3];
        if (MODE == 0) {
            float bb0 = bias[c], bb1 = bias[c + 1];
            v0 = fmaxf(v0 + bb0, 0.f); v1 = fmaxf(v1 + bb1, 0.f);
            v2 = fmaxf(v2 + bb0, 0.f); v3 = fmaxf(v3 + bb1, 0.f);
            if (r0 < N_NODES) *(float2*)&g_h1[(size_t)r0 * 128 + c] = make_float2(v0, v1);
            if (r1 < N_NODES) *(float2*)&g_h1[(size_t)r1 * 128 + c] = make_float2(v2, v3);
        } else {
            if (c < 64) {   // nbr half -> bf16x2
                if (r0 < N_NODES) g_ub[r0 * 32 + (c >> 1)] = bf2_of(v1, v0);
                if (r1 < N_NODES) g_ub[r1 * 32 + (c >> 1)] = bf2_of(v3, v2);
            } else {        // root half -> fp32
                if (r0 < N_NODES) *(float2*)&g_ur[(size_t)r0 * 64 + (c - 64)] = make_float2(v0, v1);
                if (r1 < N_NODES) *(float2*)&g_ur[(size_t)r1 * 64 + (c - 64)] = make_float2(v2, v3);
            }
        }
    }
}

// ---------------- layer-2 aggregation over bf16 u rows (+ fused final, bf16 h2) ----
__global__ __launch_bounds__(256) void k_agg2(const float* __restrict__ b2) {
    int gt = blockIdx.x * blockDim.x + threadIdx.x;
    int w = gt >> 5, lane = gt & 31;
    if (w >= N_NODES) return;
    int start = g_rowptr[w], end = start + g_deg[w];
    float ax = 0.f, ay = 0.f;
    for (int i = start; i < end; i += 32) {
        int m = min(32, end - i);
        int eid = (i + lane < end) ? g_csr[i + lane] : 0;
        for (int j = 0; j < m; j++) {
            int s = __shfl_sync(0xffffffffu, eid, j);
            float2 v = bf2f(__ldg(g_ub + (size_t)s * 32 + lane));
            ax += v.x; ay += v.y;
        }
    }
    float di = g_deginv[w];
    float rx = g_ur[(size_t)w * 64 + lane * 2];
    float ry = g_ur[(size_t)w * 64 + lane * 2 + 1];
    float o0 = rx + ax * di + b2[lane * 2];
    float o1 = ry + ay * di + b2[lane * 2 + 1];
    g_h2b[w * 32 + lane] = bf2_of(o1, o0);
}

// ---------------- edge dot over bf16 h2: warp/dst, 8 lanes/edge, 4 edges/iter ----
__global__ __launch_bounds__(256) void k_edge3(float* __restrict__ out) {
    int gt = blockIdx.x * blockDim.x + threadIdx.x;
    int w = gt >> 5, lane = gt & 31;
    if (w >= N_NODES) return;
    int g = lane >> 3;
    int k = lane & 7;
    const uint4* h4 = (const uint4*)g_h2b;   // row = 8 uint4 (64 bf16)
    uint4 dd = h4[(size_t)w * 8 + k];
    float2 d0 = bf2f(dd.x), d1 = bf2f(dd.y), d2 = bf2f(dd.z), d3 = bf2f(dd.w);
    int start = g_rowptr[w], end = start + g_deg[w];
    for (int i = start; i < end; i += 4) {
        int idx = i + g;
        bool valid = idx < end;
        int s = 0, eid = 0;
        if (valid) { s = g_csr[idx]; eid = g_eid[idx]; }
        float acc = 0.f;
        if (valid) {
            uint4 aa = __ldg(&h4[(size_t)s * 8 + k]);
            float2 a0 = bf2f(aa.x), a1 = bf2f(aa.y), a2 = bf2f(aa.z), a3 = bf2f(aa.w);
            acc = a0.x * d0.x + a0.y * d0.y + a1.x * d1.x + a1.y * d1.y
                + a2.x * d2.x + a2.y * d2.y + a3.x * d3.x + a3.y * d3.y;
        }
        acc += __shfl_xor_sync(0xffffffffu, acc, 1);
        acc += __shfl_xor_sync(0xffffffffu, acc, 2);
        acc += __shfl_xor_sync(0xffffffffu, acc, 4);
        if (valid && k == 0) out[eid] = acc;
    }
}

// ---------------- launch ----------------
extern "C" void kernel_launch(void* const* d_in, const int* in_sizes, int n_in,
                              void* d_out, int out_size) {
    const float* x   = (const float*)d_in[0];
    const float* pos = (const float*)d_in[1];
    const int*   ei  = (const int*)d_in[2];
    const float* W1r = (const float*)d_in[3];
    const float* W1n = (const float*)d_in[4];
    const float* b1  = (const float*)d_in[5];
    const float* W2r = (const float*)d_in[6];
    const float* W2n = (const float*)d_in[7];
    const float* b2  = (const float*)d_in[8];
    float* out = (float*)d_out;

    int E = in_sizes[2] / 2;
    const int* src = ei;
    const int* dst = ei + E;

    k_prepw<<<256, 256>>>(W1r, W1n, W2r, W2n, x, pos);
    k_deg<<<(E + 255) / 256, 256>>>(dst, E);
    k_base<<<(N_NODES + 255) / 256, 256>>>();
    k_fillcsr<<<(E + 255) / 256, 256>>>(src, dst, E);
    k_agg1<<<(N_NODES * 32 + 255) / 256, 256>>>(x, pos);
    k_gemm_bf<0><<<GBLK_TC, 256>>>(b1);
    k_gemm_bf<1><<<GBLK_TC, 256>>>(b1);
    k_agg2<<<(N_NODES * 32 + 255) / 256, 256>>>(b2);
    k_edge3<<<(N_NODES * 32 + 255) / 256, 256>>>(out);
}